// round 5
// baseline (speedup 1.0000x reference)
#include <cuda_runtime.h>

#define B_ 8
#define H_ 352
#define W_ 1216
#define PLANE (H_*W_)
#define NPIX (B_*PLANE)
#define MAXR 32
#define VPH 416                     // padded height (32 | 352 | 32)
#define NV (B_*VPH*W_)

// horizontal partial results (aw, awd) per pixel
__device__ float AWH[NPIX];
__device__ float AWDH[NPIX];

// vertical tables (as in R3): E = exp(+/-plog_v), GD = (g, g*depth)
__device__ float  E2[NV];  __device__ float2 GD2[NV]; // +h, var2
__device__ float  E3[NV];  __device__ float2 GD3[NV]; // -h, var3

// ---------------------------------------------------------------------------
// Horizontal fused scan kernel: one block per image row.
// ---------------------------------------------------------------------------
#define TPB 608        // 2 pixels per thread (608*2 = 1216 = W_)
#define NWARP 19

__device__ __forceinline__ double shfl_up_d(double x, int d) {
    return __shfl_up_sync(0xFFFFFFFFu, x, d);
}

__global__ void __launch_bounds__(TPB)
hscan_kernel(const float* __restrict__ pred_log,
             const int*   __restrict__ mask,
             const float* __restrict__ var,
             const float* __restrict__ depth)
{
    __shared__ double A0s[W_ + 1];   // prefix sums: S[k] = sum_{j<k} x[j]
    __shared__ double A1s[W_ + 1];
    __shared__ double G0s[W_ + 1];
    __shared__ double G1s[W_ + 1];
    __shared__ double wt[4][NWARP];  // warp totals for the 4 double scans
    __shared__ float  PEs[W_ + 1];   // PEs[k] = prod_{j<k} e[j]
    __shared__ float  wtp[NWARP];
    __shared__ unsigned int  bm[41]; // alive bitmap, bit (q+32) = pixel q unmasked
    __shared__ unsigned char alive[W_];

    const int row = blockIdx.x;          // b*H_ + h
    const int b   = row / H_;
    const int t    = threadIdx.x;
    const int lane = t & 31, wid = t >> 5;
    const int j0   = 2 * t;

    const size_t base  = (size_t)row * W_;          // into (B,1,H,W) arrays
    const size_t inrow = base - (size_t)b * PLANE;  // h*W_ within a plane

    float2 ph = *(const float2*)(pred_log + (size_t)b * 2 * PLANE + inrow + j0);
    int2   mk = *(const int2*)  (mask + base + j0);
    float2 v0 = *(const float2*)(var + (size_t)b * 4 * PLANE + inrow + j0);
    float2 v1 = *(const float2*)(var + (size_t)b * 4 * PLANE + PLANE + inrow + j0);
    float2 dd = *(const float2*)(depth + base + j0);

    float m0 = mk.x ? 1.f : 0.f, m1 = mk.y ? 1.f : 0.f;
    float e0 = expf(ph.x), e1 = expf(ph.y);
    float g00 = expf(-fminf(v0.x, 5.f)) * m0, g01 = expf(-fminf(v0.y, 5.f)) * m1;
    float g10 = expf(-fminf(v1.x, 5.f)) * m0, g11 = expf(-fminf(v1.y, 5.f)) * m1;

    alive[j0]     = mk.x ? 1 : 0;
    alive[j0 + 1] = mk.y ? 1 : 0;

    // ---- PE product scan (float) ----
    float s = e0 * e1;
    float ws = s;
    #pragma unroll
    for (int d = 1; d < 32; d <<= 1) {
        float o = __shfl_up_sync(0xFFFFFFFFu, ws, d);
        if (lane >= d) ws *= o;
    }
    if (lane == 31) wtp[wid] = ws;
    __syncthreads();
    if (wid == 0) {
        float x = (lane < NWARP) ? wtp[lane] : 1.f;
        #pragma unroll
        for (int d = 1; d < 32; d <<= 1) {
            float o = __shfl_up_sync(0xFFFFFFFFu, x, d);
            if (lane >= d) x *= o;
        }
        if (lane < NWARP) wtp[lane] = x;
    }
    __syncthreads();
    float blkp = (wid == 0) ? 1.f : wtp[wid - 1];
    float wex  = __shfl_up_sync(0xFFFFFFFFu, ws, 1);
    if (lane == 0) wex = 1.f;
    float pex = blkp * wex;              // prod of all e before j0
    PEs[j0]     = pex;
    PEs[j0 + 1] = pex * e0;
    if (t == TPB - 1) PEs[W_] = pex * e0 * e1;

    // ---- T values (local, no smem read needed) ----
    float pe0 = pex, pe1 = pex * e0;
    double t00 = (double)(g00 * dd.x) / (double)pe0;  // gd0/PE
    double t01 = (double)(g01 * dd.y) / (double)pe1;
    double t10 = (double)(g10 * dd.x) / (double)pe0;  // gd1/PE
    double t11 = (double)(g11 * dd.y) / (double)pe1;

    // ---- 4 double sum-scans ----
    {
        double x0[4] = { t00, t10, (double)g00, (double)g10 };
        double x1[4] = { t01, t11, (double)g01, (double)g11 };
        double* Sarr[4] = { A0s, A1s, G0s, G1s };
        #pragma unroll
        for (int q = 0; q < 4; ++q) {
            double sq = x0[q] + x1[q];
            double wsq = sq;
            #pragma unroll
            for (int d = 1; d < 32; d <<= 1) {
                double o = shfl_up_d(wsq, d);
                if (lane >= d) wsq += o;
            }
            if (lane == 31) wt[q][wid] = wsq;
            __syncthreads();
            if (wid == 0) {
                double x = (lane < NWARP) ? wt[q][lane] : 0.0;
                #pragma unroll
                for (int d = 1; d < 32; d <<= 1) {
                    double o = shfl_up_d(x, d);
                    if (lane >= d) x += o;
                }
                if (lane < NWARP) wt[q][lane] = x;
            }
            __syncthreads();
            double blk = (wid == 0) ? 0.0 : wt[q][wid - 1];
            double ex  = blk + (wsq - sq);
            double* S = Sarr[q];
            S[j0 + 1] = ex + x0[q];
            S[j0 + 2] = ex + x0[q] + x1[q];
            if (t == 0) S[0] = 0.0;
        }
    }

    // ---- alive bitmap (pixel q alive -> bit q+32) ----
    if (t == 0) { bm[0] = 0u; bm[39] = 0u; bm[40] = 0u; }
    __syncthreads();
    if (t < 38) {
        unsigned wbits = 0u;
        #pragma unroll 8
        for (int k = 0; k < 32; ++k)
            wbits |= (alive[32 * t + k] ? 1u : 0u) << k;
        bm[t + 1] = wbits;
    }
    __syncthreads();

    // ---- O(1) per-pixel lookups ----
    #pragma unroll
    for (int p = 0; p < 2; ++p) {
        int j = j0 + p;
        int alv = p ? mk.y : mk.x;
        if (!alv) { AWH[base + j] = 0.f; AWDH[base + j] = 0.f; continue; }

        // +w: neighbors q = j-32 .. j-1  -> bm bits j .. j+31
        unsigned u  = __funnelshift_r(bm[j >> 5], bm[(j >> 5) + 1], j & 31);
        unsigned v  = __brev(u);           // bit(k-1) = alive[j-k]
        unsigned nv = ~v;
        int lim0 = nv ? (__ffs(nv) - 1) : 32;

        // -w: neighbors q = j+1 .. j+32  -> bm bits j+33 .. j+64
        int boff = j + 33;
        unsigned u2  = __funnelshift_r(bm[boff >> 5], bm[(boff >> 5) + 1], boff & 31);
        unsigned nu2 = ~u2;
        int lim1 = nu2 ? (__ffs(nu2) - 1) : 32;

        double a = (A0s[j] - A0s[j - lim0]) + (A1s[j + 1 + lim1] - A1s[j + 1]);
        double g = (G0s[j] - G0s[j - lim0]) + (G1s[j + 1 + lim1] - G1s[j + 1]);
        AWH[base + j]  = (float)g;
        AWDH[base + j] = (float)((double)PEs[j] * a);
    }
}

// ---------------------------------------------------------------------------
// Vertical prep (unchanged from R3, zero-padded rows)
// ---------------------------------------------------------------------------
__global__ void prep_v(const float* __restrict__ pred_log,
                       const int*   __restrict__ mask,
                       const float* __restrict__ var,
                       const float* __restrict__ depth)
{
    int i = blockIdx.x * blockDim.x + threadIdx.x;
    if (i >= NV) return;
    int w   = i % W_;
    int rhp = i / W_;
    int b   = rhp / VPH;
    int h   = (rhp - b * VPH) - 32;
    if ((unsigned)h >= (unsigned)H_) {
        E2[i] = 0.f; E3[i] = 0.f;
        GD2[i] = make_float2(0.f, 0.f); GD3[i] = make_float2(0.f, 0.f);
        return;
    }
    int p = h * W_ + w;
    int idx = b * PLANE + p;
    float pv = pred_log[(size_t)b * 2 * PLANE + PLANE + p];
    float m  = mask[idx] ? 1.f : 0.f;
    float v2 = var[(size_t)b * 4 * PLANE + 2 * PLANE + p];
    float v3 = var[(size_t)b * 4 * PLANE + 3 * PLANE + p];
    float d  = depth[idx];
    float g2 = expf(-fminf(v2, 5.f)) * m;
    float g3 = expf(-fminf(v3, 5.f)) * m;
    E2[i] = expf(pv);
    E3[i] = expf(-pv);
    GD2[i] = make_float2(g2, g2 * d);
    GD3[i] = make_float2(g3, g3 * d);
}

// ---------------------------------------------------------------------------
// Vertical walk (batch-4 with break, as in R3) + combine with horizontal partials
// ---------------------------------------------------------------------------
template<bool INCL, int S>
__device__ __forceinline__ void walk(const float* __restrict__ E,
                                     const float2* __restrict__ GD,
                                     int c, float& aw, float& awd)
{
    float P = INCL ? 1.f : E[c];
    float A = 1.f;
    for (int n0 = 1; n0 <= MAXR; n0 += 4) {
        float  e[4];
        float2 g[4];
        #pragma unroll
        for (int j = 0; j < 4; ++j) {
            int off = c + (n0 + j) * S;
            e[j] = E[off];
            g[j] = GD[off];
        }
        #pragma unroll
        for (int j = 0; j < 4; ++j) {
            if (INCL) P *= e[j];
            awd += g[j].y * P;
            aw  += g[j].x * A;
            if (!INCL) P *= e[j];
            if (g[j].x == 0.f) { A = 0.f; P = 0.f; }
        }
        if (A == 0.f) break;
    }
}

__global__ void __launch_bounds__(256)
vwalk_kernel(const int*   __restrict__ mask,
             const float* __restrict__ depthin,
             const float* __restrict__ lam_p,
             float*       __restrict__ out)
{
    int w = blockIdx.x * blockDim.x + threadIdx.x;
    if (w >= W_) return;
    int h = blockIdx.y;
    int b = blockIdx.z;
    int idx = (b * H_ + h) * W_ + w;

    float din = depthin[idx];
    if (mask[idx] == 0) { out[idx] = din; return; }

    int bv = (b * VPH + 32 + h) * W_ + w;

    float aw  = AWH[idx];
    float awd = AWDH[idx];
    walk<true,  -W_>(E2, GD2, bv, aw, awd);   // +h
    walk<false, +W_>(E3, GD3, bv, aw, awd);   // -h

    float o = din;
    if (aw > 0.f) {
        float lat = awd / fmaxf(aw, 1e-12f);
        if (lat > 0.f) {
            float lam = lam_p[0];
            o = din * (1.f - lam) + lat * lam;
        }
    }
    out[idx] = o;
}

extern "C" void kernel_launch(void* const* d_in, const int* in_sizes, int n_in,
                              void* d_out, int out_size)
{
    const float* pred_log = (const float*)d_in[0];
    const int*   mask     = (const int*)  d_in[1];
    const float* variance = (const float*)d_in[2];
    const float* depthin  = (const float*)d_in[3];
    const float* lam      = (const float*)d_in[4];
    float* out = (float*)d_out;

    hscan_kernel<<<B_ * H_, TPB>>>(pred_log, mask, variance, depthin);

    const int T = 256;
    prep_v<<<(NV + T - 1) / T, T>>>(pred_log, mask, variance, depthin);

    dim3 grid((W_ + T - 1) / T, H_, B_);
    vwalk_kernel<<<grid, T>>>(mask, depthin, lam, out);
}

// round 6
// speedup vs baseline: 3.2066x; 3.2066x over previous
#include <cuda_runtime.h>

#define B_ 8
#define H_ 352
#define W_ 1216
#define PLANE (H_*W_)
#define NPIX (B_*PLANE)
#define MAXR 32

#define HPW 1280                    // padded width  (32 | 1216 | 32)
#define VPH 416                     // padded height (32 | 352  | 32)
#define NH (B_*H_*HPW)
#define NV (B_*VPH*W_)

// Per-direction tables. Border cells are NEVER written: __device__ globals are
// zero-initialized at module load, and zero entries terminate walks exactly
// like masked pixels.
//   E*  = exp(+/- plog)        GD* = (g, g*depth),  g = exp(-min(var,5))*mask
__device__ float  E0[NH];  __device__ float2 GD0[NH]; // +w, var0, exp(+plog_h)
__device__ float  E1[NH];  __device__ float2 GD1[NH]; // -w, var1, exp(-plog_h)
__device__ float  E2[NV];  __device__ float2 GD2[NV]; // +h, var2, exp(+plog_v)
__device__ float  E3[NV];  __device__ float2 GD3[NV]; // -h, var3, exp(-plog_v)

__global__ void __launch_bounds__(256)
prep_kernel(const float* __restrict__ pred_log,
            const int*   __restrict__ mask,
            const float* __restrict__ var,
            const float* __restrict__ depth)
{
    int idx = blockIdx.x * blockDim.x + threadIdx.x;
    if (idx >= NPIX) return;
    int b = idx / PLANE;
    int p = idx - b * PLANE;
    int h = p / W_;
    int w = p - h * W_;

    const float* pl = pred_log + (size_t)b * 2 * PLANE + p;
    float ph = pl[0];
    float pv = pl[PLANE];
    float m  = mask[idx] ? 1.f : 0.f;
    const float* vv = var + (size_t)b * 4 * PLANE + p;
    float v0 = vv[0];
    float v1 = vv[PLANE];
    float v2 = vv[2 * PLANE];
    float v3 = vv[3 * PLANE];
    float d  = depth[idx];

    float g0 = expf(-fminf(v0, 5.f)) * m;
    float g1 = expf(-fminf(v1, 5.f)) * m;
    float g2 = expf(-fminf(v2, 5.f)) * m;
    float g3 = expf(-fminf(v3, 5.f)) * m;

    int hi = (b * H_ + h) * HPW + 32 + w;
    int vi = (b * VPH + 32 + h) * W_ + w;

    E0[hi] = expf(ph);   GD0[hi] = make_float2(g0, g0 * d);
    E1[hi] = expf(-ph);  GD1[hi] = make_float2(g1, g1 * d);
    E2[vi] = expf(pv);   GD2[vi] = make_float2(g2, g2 * d);
    E3[vi] = expf(-pv);  GD3[vi] = make_float2(g3, g3 * d);
}

// Interleaved pair of opposite-direction walks (INCL dir uses product including
// the source step; EXCL dir excludes it). 8 independent loads per batch.
template<int S>
__device__ __forceinline__ void walk_pair(const float*  __restrict__ Ea,
                                          const float2* __restrict__ GDa,
                                          const float*  __restrict__ Eb,
                                          const float2* __restrict__ GDb,
                                          int c, float& aw, float& awd)
{
    float P0 = 1.f,      A0 = 1.f;   // INCL dir (negative stride)
    float P1 = Eb[c],    A1 = 1.f;   // EXCL dir (positive stride)
    for (int n0 = 1; n0 <= MAXR; n0 += 4) {
        float  e0[4], e1[4];
        float2 g0[4], g1[4];
        #pragma unroll
        for (int j = 0; j < 4; ++j) {
            int o = (n0 + j) * S;
            e0[j] = Ea[c - o];  g0[j] = GDa[c - o];
            e1[j] = Eb[c + o];  g1[j] = GDb[c + o];
        }
        #pragma unroll
        for (int j = 0; j < 4; ++j) {
            P0 *= e0[j];
            awd += g0[j].y * P0;
            aw  += g0[j].x * A0;
            if (g0[j].x == 0.f) { A0 = 0.f; P0 = 0.f; }

            awd += g1[j].y * P1;
            aw  += g1[j].x * A1;
            P1 *= e1[j];
            if (g1[j].x == 0.f) { A1 = 0.f; P1 = 0.f; }
        }
        if (A0 == 0.f && A1 == 0.f) break;
    }
}

__global__ void __launch_bounds__(256)
crf_kernel(const int*   __restrict__ mask,
           const float* __restrict__ depthin,
           const float* __restrict__ lam_p,
           float*       __restrict__ out)
{
    int w = blockIdx.x * 32 + threadIdx.x;
    int h = blockIdx.y * 8  + threadIdx.y;
    int b = blockIdx.z;
    int idx = (b * H_ + h) * W_ + w;

    float din = depthin[idx];
    if (mask[idx] == 0) { out[idx] = din; return; }

    int bh = (b * H_ + h) * HPW + 32 + w;
    int bv = (b * VPH + 32 + h) * W_ + w;

    float aw = 0.f, awd = 0.f;
    walk_pair<1  >(E0, GD0, E1, GD1, bh, aw, awd);   // +w / -w
    walk_pair<W_ >(E2, GD2, E3, GD3, bv, aw, awd);   // +h / -h

    float o = din;
    if (aw > 0.f) {
        float lat = awd / fmaxf(aw, 1e-12f);
        if (lat > 0.f) {
            float lam = lam_p[0];
            o = din * (1.f - lam) + lat * lam;
        }
    }
    out[idx] = o;
}

extern "C" void kernel_launch(void* const* d_in, const int* in_sizes, int n_in,
                              void* d_out, int out_size)
{
    const float* pred_log = (const float*)d_in[0];
    const int*   mask     = (const int*)  d_in[1];
    const float* variance = (const float*)d_in[2];
    const float* depthin  = (const float*)d_in[3];
    const float* lam      = (const float*)d_in[4];
    float* out = (float*)d_out;

    const int T = 256;
    prep_kernel<<<(NPIX + T - 1) / T, T>>>(pred_log, mask, variance, depthin);

    dim3 blk(32, 8);
    dim3 grid(W_ / 32, H_ / 8, B_);
    crf_kernel<<<grid, blk>>>(mask, depthin, lam, out);
}

// round 7
// speedup vs baseline: 3.5477x; 1.1064x over previous
#include <cuda_runtime.h>
#include <cuda_fp16.h>

#define B_ 8
#define H_ 352
#define W_ 1216
#define PLANE (H_*W_)
#define NPIX (B_*PLANE)
#define MAXR 32

#define HPW 1280                    // padded width  (32 | 1216 | 32)
#define VPH 416                     // padded height (32 | 352  | 32)
#define NH (B_*H_*HPW)
#define NV (B_*VPH*W_)

// Per-direction tables. Border cells are NEVER written: __device__ globals are
// zero-initialized at module load; zero g terminates walks like masked pixels.
//   E*  = exp(+/- plog) (fp32)   GD* = half2(g, g*depth), g = exp(-min(var,5))*mask
__device__ float   E0[NH];  __device__ __half2 GD0[NH]; // +w, var0, exp(+plog_h)
__device__ float   E1[NH];  __device__ __half2 GD1[NH]; // -w, var1, exp(-plog_h)
__device__ float   E2[NV];  __device__ __half2 GD2[NV]; // +h, var2, exp(+plog_v)
__device__ float   E3[NV];  __device__ __half2 GD3[NV]; // -h, var3, exp(-plog_v)

__global__ void __launch_bounds__(256)
prep_kernel(const float* __restrict__ pred_log,
            const int*   __restrict__ mask,
            const float* __restrict__ var,
            const float* __restrict__ depth)
{
    int idx = blockIdx.x * blockDim.x + threadIdx.x;
    if (idx >= NPIX) return;
    int b = idx / PLANE;
    int p = idx - b * PLANE;
    int h = p / W_;
    int w = p - h * W_;

    const float* pl = pred_log + (size_t)b * 2 * PLANE + p;
    float ph = pl[0];
    float pv = pl[PLANE];
    float m  = mask[idx] ? 1.f : 0.f;
    const float* vv = var + (size_t)b * 4 * PLANE + p;
    float v0 = vv[0];
    float v1 = vv[PLANE];
    float v2 = vv[2 * PLANE];
    float v3 = vv[3 * PLANE];
    float d  = depth[idx];

    float g0 = expf(-fminf(v0, 5.f)) * m;
    float g1 = expf(-fminf(v1, 5.f)) * m;
    float g2 = expf(-fminf(v2, 5.f)) * m;
    float g3 = expf(-fminf(v3, 5.f)) * m;

    int hi = (b * H_ + h) * HPW + 32 + w;
    int vi = (b * VPH + 32 + h) * W_ + w;

    E0[hi] = expf(ph);   GD0[hi] = __floats2half2_rn(g0, g0 * d);
    E1[hi] = expf(-ph);  GD1[hi] = __floats2half2_rn(g1, g1 * d);
    E2[vi] = expf(pv);   GD2[vi] = __floats2half2_rn(g2, g2 * d);
    E3[vi] = expf(-pv);  GD3[vi] = __floats2half2_rn(g3, g3 * d);
}

// One directional walk: batch-4 independent loads, kill-selects in the batch,
// early break between batches. INCL = log-factor product includes source step.
template<bool INCL, int S>
__device__ __forceinline__ void walk(const float*   __restrict__ E,
                                     const __half2* __restrict__ GD,
                                     int c, float& aw, float& awd)
{
    float P = INCL ? 1.f : E[c];
    float A = 1.f;
    for (int n0 = 1; n0 <= MAXR; n0 += 4) {
        float  e[4];
        float2 g[4];
        #pragma unroll
        for (int j = 0; j < 4; ++j) {
            int off = c + (n0 + j) * S;
            e[j] = E[off];
            g[j] = __half22float2(GD[off]);
        }
        #pragma unroll
        for (int j = 0; j < 4; ++j) {
            if (INCL) P *= e[j];
            awd += g[j].y * P;
            aw  += g[j].x * A;
            if (!INCL) P *= e[j];
            if (g[j].x == 0.f) { A = 0.f; P = 0.f; }
        }
        if (A == 0.f) break;
    }
}

__global__ void __launch_bounds__(256)
crf_kernel(const int*   __restrict__ mask,
           const float* __restrict__ depthin,
           const float* __restrict__ lam_p,
           float*       __restrict__ out)
{
    int w = blockIdx.x * 32 + threadIdx.x;
    int h = blockIdx.y * 8  + threadIdx.y;
    int b = blockIdx.z;
    int idx = (b * H_ + h) * W_ + w;

    float din = depthin[idx];
    if (mask[idx] == 0) { out[idx] = din; return; }

    int bh = (b * H_ + h) * HPW + 32 + w;
    int bv = (b * VPH + 32 + h) * W_ + w;

    float aw = 0.f, awd = 0.f;
    walk<true,  -1 >(E0, GD0, bh, aw, awd);   // +w
    walk<false, +1 >(E1, GD1, bh, aw, awd);   // -w
    walk<true,  -W_>(E2, GD2, bv, aw, awd);   // +h
    walk<false, +W_>(E3, GD3, bv, aw, awd);   // -h

    float o = din;
    if (aw > 0.f) {
        float lat = awd / fmaxf(aw, 1e-12f);
        if (lat > 0.f) {
            float lam = lam_p[0];
            o = din * (1.f - lam) + lat * lam;
        }
    }
    out[idx] = o;
}

extern "C" void kernel_launch(void* const* d_in, const int* in_sizes, int n_in,
                              void* d_out, int out_size)
{
    const float* pred_log = (const float*)d_in[0];
    const int*   mask     = (const int*)  d_in[1];
    const float* variance = (const float*)d_in[2];
    const float* depthin  = (const float*)d_in[3];
    const float* lam      = (const float*)d_in[4];
    float* out = (float*)d_out;

    const int T = 256;
    prep_kernel<<<(NPIX + T - 1) / T, T>>>(pred_log, mask, variance, depthin);

    dim3 blk(32, 8);
    dim3 grid(W_ / 32, H_ / 8, B_);
    crf_kernel<<<grid, blk>>>(mask, depthin, lam, out);
}

// round 8
// speedup vs baseline: 3.6343x; 1.0244x over previous
#include <cuda_runtime.h>
#include <cuda_fp16.h>

#define B_ 8
#define H_ 352
#define W_ 1216
#define PLANE (H_*W_)
#define NPIX (B_*PLANE)
#define MAXR 32

#define HPW 1280                    // padded width  (32 | 1216 | 32)
#define VPH 416                     // padded height (32 | 352  | 32)
#define NH (B_*H_*HPW)
#define NVT (B_*W_*VPH)             // transposed vertical tables

// Packed per-direction table element (8 B): .x = exp(+/-plog)*mask (fp32),
// .y = bitcast half2(g, g*depth), g = exp(-min(var,5))*mask.
// Border cells are never written -> zero -> walks die there like masked pixels.
// Since .x is pre-masked, the running log-gradient product self-kills (P*=0).
__device__ float2 T0[NH];   // +w, var0, exp(+plog_h)   layout (b,h,w) padded
__device__ float2 T1[NH];   // -w, var1, exp(-plog_h)
__device__ float2 T2[NVT];  // +h, var2, exp(+plog_v)   TRANSPOSED (b,w,h) padded
__device__ float2 T3[NVT];  // -h, var3, exp(-plog_v)
__device__ float2 PH[NPIX]; // vertical partial (aw, awd), normal (b,h,w) layout

__device__ __forceinline__ float2 pack(float e, float g, float gd) {
    __half2 h2 = __floats2half2_rn(g, gd);
    float2 r;
    r.x = e;
    r.y = __uint_as_float(*reinterpret_cast<unsigned*>(&h2));
    return r;
}

__global__ void __launch_bounds__(256)
prep_kernel(const float* __restrict__ pred_log,
            const int*   __restrict__ mask,
            const float* __restrict__ var,
            const float* __restrict__ depth)
{
    int idx = blockIdx.x * blockDim.x + threadIdx.x;
    if (idx >= NPIX) return;
    int b = idx / PLANE;
    int p = idx - b * PLANE;
    int h = p / W_;
    int w = p - h * W_;

    const float* pl = pred_log + (size_t)b * 2 * PLANE + p;
    float ph = pl[0];
    float pv = pl[PLANE];
    float m  = mask[idx] ? 1.f : 0.f;
    const float* vv = var + (size_t)b * 4 * PLANE + p;
    float v0 = vv[0];
    float v1 = vv[PLANE];
    float v2 = vv[2 * PLANE];
    float v3 = vv[3 * PLANE];
    float d  = depth[idx];

    float g0 = expf(-fminf(v0, 5.f)) * m;
    float g1 = expf(-fminf(v1, 5.f)) * m;
    float g2 = expf(-fminf(v2, 5.f)) * m;
    float g3 = expf(-fminf(v3, 5.f)) * m;

    int hi = (b * H_ + h) * HPW + 32 + w;
    int vi = (b * W_ + w) * VPH + 32 + h;

    T0[hi] = pack(expf(ph)  * m, g0, g0 * d);
    T1[hi] = pack(expf(-ph) * m, g1, g1 * d);
    T2[vi] = pack(expf(pv)  * m, g2, g2 * d);
    T3[vi] = pack(expf(-pv) * m, g3, g3 * d);
}

// One directional walk over a packed table. INCL = product includes source step.
// S = element stride toward the sources. Batch-4 loads, break between batches.
template<bool INCL, int S>
__device__ __forceinline__ void walk(const float2* __restrict__ T,
                                     int c, float& aw, float& awd)
{
    float P = INCL ? 1.f : T[c].x;
    float A = 1.f;
    for (int n0 = 1; n0 <= MAXR; n0 += 4) {
        float2 t[4];
        #pragma unroll
        for (int j = 0; j < 4; ++j) t[j] = T[c + (n0 + j) * S];
        #pragma unroll
        for (int j = 0; j < 4; ++j) {
            unsigned u = __float_as_uint(t[j].y);
            __half2 h2 = *reinterpret_cast<__half2*>(&u);
            float2 g = __half22float2(h2);
            if (INCL) P *= t[j].x;      // pre-masked e: self-kills P on dead pixel
            awd += g.y * P;
            aw  += g.x * A;
            if (!INCL) P *= t[j].x;
            if (g.x == 0.f) A = 0.f;    // alive product for aw
        }
        if (A == 0.f) break;
    }
}

// Vertical walks in transposed frame: lanes span h -> correlated warp breaks.
__global__ void __launch_bounds__(256)
vwalk_kernel()
{
    int h = blockIdx.x * 32 + threadIdx.x;
    int w = blockIdx.y * 8  + threadIdx.y;
    int b = blockIdx.z;

    int c = (b * W_ + w) * VPH + 32 + h;
    float aw = 0.f, awd = 0.f;
    walk<true,  -1>(T2, c, aw, awd);   // +h (sources at h-n)
    walk<false, +1>(T3, c, aw, awd);   // -h (sources at h+n)

    // smem tile transpose -> coalesced write of partials in normal layout
    __shared__ float2 tile[32][9];
    tile[threadIdx.x][threadIdx.y] = make_float2(aw, awd);
    __syncthreads();
    int t  = threadIdx.y * 32 + threadIdx.x;
    int hl = t >> 3, wl = t & 7;
    int h0 = blockIdx.x * 32, w0 = blockIdx.y * 8;
    PH[(b * H_ + h0 + hl) * W_ + w0 + wl] = tile[hl][wl];
}

// Horizontal walks + combine + final blend. Lanes span w.
__global__ void __launch_bounds__(256)
hwalk_kernel(const int*   __restrict__ mask,
             const float* __restrict__ depthin,
             const float* __restrict__ lam_p,
             float*       __restrict__ out)
{
    int w = blockIdx.x * 32 + threadIdx.x;
    int h = blockIdx.y * 8  + threadIdx.y;
    int b = blockIdx.z;
    int idx = (b * H_ + h) * W_ + w;

    float din = depthin[idx];
    float2 pv = PH[idx];
    if (mask[idx] == 0) { out[idx] = din; return; }

    int c = (b * H_ + h) * HPW + 32 + w;
    float aw = pv.x, awd = pv.y;
    walk<true,  -1>(T0, c, aw, awd);   // +w
    walk<false, +1>(T1, c, aw, awd);   // -w

    float o = din;
    if (aw > 0.f) {
        float lat = awd / fmaxf(aw, 1e-12f);
        if (lat > 0.f) {
            float lam = lam_p[0];
            o = din * (1.f - lam) + lat * lam;
        }
    }
    out[idx] = o;
}

extern "C" void kernel_launch(void* const* d_in, const int* in_sizes, int n_in,
                              void* d_out, int out_size)
{
    const float* pred_log = (const float*)d_in[0];
    const int*   mask     = (const int*)  d_in[1];
    const float* variance = (const float*)d_in[2];
    const float* depthin  = (const float*)d_in[3];
    const float* lam      = (const float*)d_in[4];
    float* out = (float*)d_out;

    const int T = 256;
    prep_kernel<<<(NPIX + T - 1) / T, T>>>(pred_log, mask, variance, depthin);

    dim3 blkv(32, 8);
    dim3 gv(H_ / 32, W_ / 8, B_);          // 11 x 152 x 8
    vwalk_kernel<<<gv, blkv>>>();

    dim3 blkh(32, 8);
    dim3 gh(W_ / 32, H_ / 8, B_);          // 38 x 44 x 8
    hwalk_kernel<<<gh, blkh>>>(mask, depthin, lam, out);
}

// round 9
// speedup vs baseline: 4.1303x; 1.1365x over previous
#include <cuda_runtime.h>
#include <cuda_fp16.h>

#define B_ 8
#define H_ 352
#define W_ 1216
#define PLANE (H_*W_)
#define NPIX (B_*PLANE)
#define MAXR 32

#define HPW 1280                    // padded width  (32 | 1216 | 32)
#define VPH 416                     // padded height (32 | 352  | 32)
#define NH (B_*H_*HPW)
#define NVT (B_*W_*VPH)             // transposed vertical tables

// Packed per-direction table element (8 B): .x = exp(+/-plog)*mask (fp32),
// .y = bitcast half2(g, g*depth), g = exp(-min(var,5))*mask.
// Border cells are never written -> zero -> walks die there like masked pixels.
__device__ float2 T0[NH];   // +w, var0, exp(+plog_h)   layout (b,h,w) padded
__device__ float2 T1[NH];   // -w, var1, exp(-plog_h)
__device__ float2 T2[NVT];  // +h, var2, exp(+plog_v)   TRANSPOSED (b,w,h) padded
__device__ float2 T3[NVT];  // -h, var3, exp(-plog_v)
__device__ float2 PH[NPIX]; // vertical partial (aw, awd), normal (b,h,w) layout

__device__ __forceinline__ float2 pack(float e, float g, float gd) {
    __half2 h2 = __floats2half2_rn(g, gd);
    float2 r;
    r.x = e;
    r.y = __uint_as_float(*reinterpret_cast<unsigned*>(&h2));
    return r;
}

// 32x32 tile per block; inputs + T0/T1 coalesced along w, T2/T3 written
// coalesced along h through an smem transpose.
__global__ void __launch_bounds__(256)
prep_kernel(const float* __restrict__ pred_log,
            const int*   __restrict__ mask,
            const float* __restrict__ var,
            const float* __restrict__ depth)
{
    __shared__ float2 s2[32][33];
    __shared__ float2 s3[32][33];

    const int b  = blockIdx.z;
    const int w0 = blockIdx.x * 32;
    const int h0 = blockIdx.y * 32;
    const int tx = threadIdx.x, ty = threadIdx.y;
    const int w  = w0 + tx;

    const float* pl0 = pred_log + (size_t)b * 2 * PLANE;
    const float* vv0 = var      + (size_t)b * 4 * PLANE;

    #pragma unroll
    for (int k = 0; k < 4; ++k) {
        int h = h0 + ty + 8 * k;
        int p = h * W_ + w;
        int idx = b * PLANE + p;

        float ph = pl0[p];
        float pv = pl0[PLANE + p];
        float m  = mask[idx] ? 1.f : 0.f;
        float v0 = vv0[p];
        float v1 = vv0[PLANE + p];
        float v2 = vv0[2 * PLANE + p];
        float v3 = vv0[3 * PLANE + p];
        float d  = depth[idx];

        float g0 = expf(-fminf(v0, 5.f)) * m;
        float g1 = expf(-fminf(v1, 5.f)) * m;
        float g2 = expf(-fminf(v2, 5.f)) * m;
        float g3 = expf(-fminf(v3, 5.f)) * m;

        int hi = (b * H_ + h) * HPW + 32 + w;
        T0[hi] = pack(expf(ph)  * m, g0, g0 * d);
        T1[hi] = pack(expf(-ph) * m, g1, g1 * d);

        s2[tx][ty + 8 * k] = pack(expf(pv)  * m, g2, g2 * d);   // [w_local][h_local]
        s3[tx][ty + 8 * k] = pack(expf(-pv) * m, g3, g3 * d);
    }
    __syncthreads();

    #pragma unroll
    for (int k = 0; k < 4; ++k) {
        int wl = ty + 8 * k;                 // w_local
        int vi = (b * W_ + w0 + wl) * VPH + 32 + h0 + tx;   // contiguous in tx
        T2[vi] = s2[wl][tx];
        T3[vi] = s3[wl][tx];
    }
}

// One directional walk over a packed table. INCL = product includes source step.
// S = element stride toward the sources. Batch-4 loads, break between batches.
template<bool INCL, int S>
__device__ __forceinline__ void walk(const float2* __restrict__ T,
                                     int c, float& aw, float& awd)
{
    float P = INCL ? 1.f : T[c].x;
    float A = 1.f;
    for (int n0 = 1; n0 <= MAXR; n0 += 4) {
        float2 t[4];
        #pragma unroll
        for (int j = 0; j < 4; ++j) t[j] = T[c + (n0 + j) * S];
        #pragma unroll
        for (int j = 0; j < 4; ++j) {
            unsigned u = __float_as_uint(t[j].y);
            __half2 h2 = *reinterpret_cast<__half2*>(&u);
            float2 g = __half22float2(h2);
            if (INCL) P *= t[j].x;      // pre-masked e: self-kills P on dead pixel
            awd += g.y * P;
            aw  += g.x * A;
            if (!INCL) P *= t[j].x;
            if (g.x == 0.f) A = 0.f;
        }
        if (A == 0.f) break;
    }
}

// Vertical walks in transposed frame: lanes span h -> correlated warp breaks.
__global__ void __launch_bounds__(256)
vwalk_kernel()
{
    int h = blockIdx.x * 32 + threadIdx.x;
    int w = blockIdx.y * 8  + threadIdx.y;
    int b = blockIdx.z;

    int c = (b * W_ + w) * VPH + 32 + h;
    float aw = 0.f, awd = 0.f;
    walk<true,  -1>(T2, c, aw, awd);   // +h (sources at h-n)
    walk<false, +1>(T3, c, aw, awd);   // -h (sources at h+n)

    // smem tile transpose -> coalesced write of partials in normal layout
    __shared__ float2 tile[32][9];
    tile[threadIdx.x][threadIdx.y] = make_float2(aw, awd);
    __syncthreads();
    int t  = threadIdx.y * 32 + threadIdx.x;
    int hl = t >> 3, wl = t & 7;
    int h0 = blockIdx.x * 32, w0 = blockIdx.y * 8;
    PH[(b * H_ + h0 + hl) * W_ + w0 + wl] = tile[hl][wl];
}

// Horizontal walks + combine + final blend. Lanes span w.
__global__ void __launch_bounds__(256)
hwalk_kernel(const int*   __restrict__ mask,
             const float* __restrict__ depthin,
             const float* __restrict__ lam_p,
             float*       __restrict__ out)
{
    int w = blockIdx.x * 32 + threadIdx.x;
    int h = blockIdx.y * 8  + threadIdx.y;
    int b = blockIdx.z;
    int idx = (b * H_ + h) * W_ + w;

    float din = depthin[idx];
    float2 pv = PH[idx];
    if (mask[idx] == 0) { out[idx] = din; return; }

    int c = (b * H_ + h) * HPW + 32 + w;
    float aw = pv.x, awd = pv.y;
    walk<true,  -1>(T0, c, aw, awd);   // +w
    walk<false, +1>(T1, c, aw, awd);   // -w

    float o = din;
    if (aw > 0.f) {
        float lat = awd / fmaxf(aw, 1e-12f);
        if (lat > 0.f) {
            float lam = lam_p[0];
            o = din * (1.f - lam) + lat * lam;
        }
    }
    out[idx] = o;
}

extern "C" void kernel_launch(void* const* d_in, const int* in_sizes, int n_in,
                              void* d_out, int out_size)
{
    const float* pred_log = (const float*)d_in[0];
    const int*   mask     = (const int*)  d_in[1];
    const float* variance = (const float*)d_in[2];
    const float* depthin  = (const float*)d_in[3];
    const float* lam      = (const float*)d_in[4];
    float* out = (float*)d_out;

    dim3 blkp(32, 8);
    dim3 gp(W_ / 32, H_ / 32, B_);         // 38 x 11 x 8
    prep_kernel<<<gp, blkp>>>(pred_log, mask, variance, depthin);

    dim3 blkv(32, 8);
    dim3 gv(H_ / 32, W_ / 8, B_);          // 11 x 152 x 8
    vwalk_kernel<<<gv, blkv>>>();

    dim3 blkh(32, 8);
    dim3 gh(W_ / 32, H_ / 8, B_);          // 38 x 44 x 8
    hwalk_kernel<<<gh, blkh>>>(mask, depthin, lam, out);
}

// round 10
// speedup vs baseline: 4.5921x; 1.1118x over previous
#include <cuda_runtime.h>
#include <cuda_fp16.h>

#define B_ 8
#define H_ 352
#define W_ 1216
#define PLANE (H_*W_)
#define NPIX (B_*PLANE)
#define MAXR 32

#define HPW 1280                    // padded width  (32 | 1216 | 32)
#define VPH 416                     // padded height (32 | 352  | 32)
#define NH (B_*H_*HPW)
#define NVT (B_*W_*VPH)             // transposed vertical tables

// Packed per-direction table element (8 B): .x = exp(+/-plog)*mask (fp32),
// .y = bitcast half2(g, g*depth), g = exp(-min(var,5))*mask.
// Border cells are never written -> zero -> walks die there like masked pixels.
// Because .x is pre-masked, the running product P==0 exactly when the path has
// crossed a dead pixel -> P doubles as the alive flag.
__device__ float2 T0[NH];   // +w, var0, exp(+plog_h)   layout (b,h,w) padded
__device__ float2 T1[NH];   // -w, var1, exp(-plog_h)
__device__ float2 T2[NVT];  // +h, var2, exp(+plog_v)   TRANSPOSED (b,w,h) padded
__device__ float2 T3[NVT];  // -h, var3, exp(-plog_v)

__device__ __forceinline__ float2 pack(float e, float g, float gd) {
    __half2 h2 = __floats2half2_rn(g, gd);
    float2 r;
    r.x = e;
    r.y = __uint_as_float(*reinterpret_cast<unsigned*>(&h2));
    return r;
}

// 32x32 tile per block; inputs + T0/T1 coalesced along w, T2/T3 written
// coalesced along h through an smem transpose.
__global__ void __launch_bounds__(256)
prep_kernel(const float* __restrict__ pred_log,
            const int*   __restrict__ mask,
            const float* __restrict__ var,
            const float* __restrict__ depth)
{
    __shared__ float2 s2[32][33];
    __shared__ float2 s3[32][33];

    const int b  = blockIdx.z;
    const int w0 = blockIdx.x * 32;
    const int h0 = blockIdx.y * 32;
    const int tx = threadIdx.x, ty = threadIdx.y;
    const int w  = w0 + tx;

    const float* pl0 = pred_log + (size_t)b * 2 * PLANE;
    const float* vv0 = var      + (size_t)b * 4 * PLANE;

    #pragma unroll
    for (int k = 0; k < 4; ++k) {
        int h = h0 + ty + 8 * k;
        int p = h * W_ + w;
        int idx = b * PLANE + p;

        float ph = pl0[p];
        float pv = pl0[PLANE + p];
        float m  = mask[idx] ? 1.f : 0.f;
        float v0 = vv0[p];
        float v1 = vv0[PLANE + p];
        float v2 = vv0[2 * PLANE + p];
        float v3 = vv0[3 * PLANE + p];
        float d  = depth[idx];

        float g0 = expf(-fminf(v0, 5.f)) * m;
        float g1 = expf(-fminf(v1, 5.f)) * m;
        float g2 = expf(-fminf(v2, 5.f)) * m;
        float g3 = expf(-fminf(v3, 5.f)) * m;

        int hi = (b * H_ + h) * HPW + 32 + w;
        T0[hi] = pack(expf(ph)  * m, g0, g0 * d);
        T1[hi] = pack(expf(-ph) * m, g1, g1 * d);

        s2[tx][ty + 8 * k] = pack(expf(pv)  * m, g2, g2 * d);   // [w_local][h_local]
        s3[tx][ty + 8 * k] = pack(expf(-pv) * m, g3, g3 * d);
    }
    __syncthreads();

    #pragma unroll
    for (int k = 0; k < 4; ++k) {
        int wl = ty + 8 * k;                 // w_local
        int vi = (b * W_ + w0 + wl) * VPH + 32 + h0 + tx;   // contiguous in tx
        T2[vi] = s2[wl][tx];
        T3[vi] = s3[wl][tx];
    }
}

// One directional walk. INCL = product includes source step. S = stride toward
// sources. Batch-4 independent loads; P==0 doubles as the dead-path flag.
template<bool INCL, int S>
__device__ __forceinline__ void walk(const float2* __restrict__ T,
                                     int c, float& aw, float& awd)
{
    float P = INCL ? 1.f : T[c].x;
    for (int n0 = 1; n0 <= MAXR; n0 += 4) {
        float2 t[4];
        #pragma unroll
        for (int j = 0; j < 4; ++j) t[j] = T[c + (n0 + j) * S];
        #pragma unroll
        for (int j = 0; j < 4; ++j) {
            unsigned u = __float_as_uint(t[j].y);
            __half2 h2 = *reinterpret_cast<__half2*>(&u);
            float2 g = __half22float2(h2);
            if (INCL) P *= t[j].x;
            awd += g.y * P;
            if (P != 0.f) aw += g.x;
            if (!INCL) P *= t[j].x;
        }
        if (P == 0.f) break;
    }
}

// Fused walk kernel: 32x32 pixel tile per 256-thread block.
// Phase 1: vertical walks, lanes along h (coalesced in transposed tables).
// Phase 2: remap, horizontal walks with lanes along w, blend, write out.
__global__ void __launch_bounds__(256)
walk_kernel(const int*   __restrict__ mask,
            const float* __restrict__ depthin,
            const float* __restrict__ lam_p,
            float*       __restrict__ out)
{
    __shared__ float s_aw [32][33];   // [h_local][w_local]
    __shared__ float s_awd[32][33];

    const int b  = blockIdx.z;
    const int w0 = blockIdx.x * 32;
    const int h0 = blockIdx.y * 32;
    const int tx = threadIdx.x, ty = threadIdx.y;

    // Phase 1: vertical walks. Thread handles (h = h0+tx, w = w0+ty+8k).
    #pragma unroll
    for (int k = 0; k < 4; ++k) {
        int wl = ty + 8 * k;
        int c = (b * W_ + w0 + wl) * VPH + 32 + h0 + tx;
        float aw = 0.f, awd = 0.f;
        walk<true,  -1>(T2, c, aw, awd);   // +h (sources at h-n)
        walk<false, +1>(T3, c, aw, awd);   // -h (sources at h+n)
        s_aw [tx][wl] = aw;
        s_awd[tx][wl] = awd;
    }
    __syncthreads();

    // Phase 2: horizontal walks. Thread handles (w = w0+tx, h = h0+ty+8k).
    const float lam = lam_p[0];
    #pragma unroll
    for (int k = 0; k < 4; ++k) {
        int hl = ty + 8 * k;
        int h = h0 + hl;
        int w = w0 + tx;
        int idx = (b * H_ + h) * W_ + w;

        float din = depthin[idx];
        if (mask[idx] == 0) { out[idx] = din; continue; }

        int c = (b * H_ + h) * HPW + 32 + w;
        float aw  = s_aw [hl][tx];
        float awd = s_awd[hl][tx];
        walk<true,  -1>(T0, c, aw, awd);   // +w
        walk<false, +1>(T1, c, aw, awd);   // -w

        float o = din;
        if (aw > 0.f) {
            float lat = awd / fmaxf(aw, 1e-12f);
            if (lat > 0.f)
                o = din * (1.f - lam) + lat * lam;
        }
        out[idx] = o;
    }
}

extern "C" void kernel_launch(void* const* d_in, const int* in_sizes, int n_in,
                              void* d_out, int out_size)
{
    const float* pred_log = (const float*)d_in[0];
    const int*   mask     = (const int*)  d_in[1];
    const float* variance = (const float*)d_in[2];
    const float* depthin  = (const float*)d_in[3];
    const float* lam      = (const float*)d_in[4];
    float* out = (float*)d_out;

    dim3 blk(32, 8);
    dim3 grid(W_ / 32, H_ / 32, B_);       // 38 x 11 x 8
    prep_kernel<<<grid, blk>>>(pred_log, mask, variance, depthin);
    walk_kernel<<<grid, blk>>>(mask, depthin, lam, out);
}

// round 11
// speedup vs baseline: 4.5943x; 1.0005x over previous
#include <cuda_runtime.h>
#include <cuda_fp16.h>

#define B_ 8
#define H_ 352
#define W_ 1216
#define PLANE (H_*W_)
#define NPIX (B_*PLANE)
#define MAXR 32

#define HPW 1280                    // padded width  (32 | 1216 | 32)
#define VPH 416                     // padded height (32 | 352  | 32)
#define NH (B_*H_*HPW)
#define NVT (B_*W_*VPH)             // transposed vertical tables

// Packed per-direction table element (8 B): .x = exp(+/-plog)*mask (fp32),
// .y = bitcast half2(g, g*depth), g = exp(-min(var,5))*mask.
// Border cells are never written -> zero -> walks die there like masked pixels.
// Because .x is pre-masked, the running product P==0 exactly when the path has
// crossed a dead pixel -> P doubles as the alive flag.
__device__ float2 T0[NH];   // +w, var0, exp(+plog_h)   layout (b,h,w) padded
__device__ float2 T1[NH];   // -w, var1, exp(-plog_h)
__device__ float2 T2[NVT];  // +h, var2, exp(+plog_v)   TRANSPOSED (b,w,h) padded
__device__ float2 T3[NVT];  // -h, var3, exp(-plog_v)

__device__ __forceinline__ float2 pack(float e, float g, float gd) {
    __half2 h2 = __floats2half2_rn(g, gd);
    float2 r;
    r.x = e;
    r.y = __uint_as_float(*reinterpret_cast<unsigned*>(&h2));
    return r;
}

// 32x32 tile per block; inputs + T0/T1 coalesced along w, T2/T3 written
// coalesced along h through an smem transpose.
__global__ void __launch_bounds__(256)
prep_kernel(const float* __restrict__ pred_log,
            const int*   __restrict__ mask,
            const float* __restrict__ var,
            const float* __restrict__ depth)
{
    __shared__ float2 s2[32][33];
    __shared__ float2 s3[32][33];

    const int b  = blockIdx.z;
    const int w0 = blockIdx.x * 32;
    const int h0 = blockIdx.y * 32;
    const int tx = threadIdx.x, ty = threadIdx.y;
    const int w  = w0 + tx;

    const float* pl0 = pred_log + (size_t)b * 2 * PLANE;
    const float* vv0 = var      + (size_t)b * 4 * PLANE;

    #pragma unroll
    for (int k = 0; k < 4; ++k) {
        int h = h0 + ty + 8 * k;
        int p = h * W_ + w;
        int idx = b * PLANE + p;

        float ph = pl0[p];
        float pv = pl0[PLANE + p];
        float m  = mask[idx] ? 1.f : 0.f;
        float v0 = vv0[p];
        float v1 = vv0[PLANE + p];
        float v2 = vv0[2 * PLANE + p];
        float v3 = vv0[3 * PLANE + p];
        float d  = depth[idx];

        float g0 = expf(-fminf(v0, 5.f)) * m;
        float g1 = expf(-fminf(v1, 5.f)) * m;
        float g2 = expf(-fminf(v2, 5.f)) * m;
        float g3 = expf(-fminf(v3, 5.f)) * m;

        int hi = (b * H_ + h) * HPW + 32 + w;
        T0[hi] = pack(expf(ph)  * m, g0, g0 * d);
        T1[hi] = pack(expf(-ph) * m, g1, g1 * d);

        s2[tx][ty + 8 * k] = pack(expf(pv)  * m, g2, g2 * d);   // [w_local][h_local]
        s3[tx][ty + 8 * k] = pack(expf(-pv) * m, g3, g3 * d);
    }
    __syncthreads();

    #pragma unroll
    for (int k = 0; k < 4; ++k) {
        int wl = ty + 8 * k;                 // w_local
        int vi = (b * W_ + w0 + wl) * VPH + 32 + h0 + tx;   // contiguous in tx
        T2[vi] = s2[wl][tx];
        T3[vi] = s3[wl][tx];
    }
}

// One directional walk. INCL = product includes source step. S = stride toward
// sources. Batch-4 independent loads; P==0 doubles as the dead-path flag.
template<bool INCL, int S>
__device__ __forceinline__ void walk(const float2* __restrict__ T,
                                     int c, float& aw, float& awd)
{
    float P = INCL ? 1.f : T[c].x;
    for (int n0 = 1; n0 <= MAXR; n0 += 4) {
        float2 t[4];
        #pragma unroll
        for (int j = 0; j < 4; ++j) t[j] = T[c + (n0 + j) * S];
        #pragma unroll
        for (int j = 0; j < 4; ++j) {
            unsigned u = __float_as_uint(t[j].y);
            __half2 h2 = *reinterpret_cast<__half2*>(&u);
            float2 g = __half22float2(h2);
            if (INCL) P *= t[j].x;
            awd += g.y * P;
            if (P != 0.f) aw += g.x;
            if (!INCL) P *= t[j].x;
        }
        if (P == 0.f) break;
    }
}

// Fused walk kernel: 32x32 pixel tile per 256-thread block.
// Phase 1: vertical walks, lanes along h (coalesced in transposed tables).
// Phase 2: remap, horizontal walks with lanes along w, blend, write out.
__global__ void __launch_bounds__(256)
walk_kernel(const int*   __restrict__ mask,
            const float* __restrict__ depthin,
            const float* __restrict__ lam_p,
            float*       __restrict__ out)
{
    __shared__ float s_aw [32][33];   // [h_local][w_local]
    __shared__ float s_awd[32][33];

    const int b  = blockIdx.z;
    const int w0 = blockIdx.x * 32;
    const int h0 = blockIdx.y * 32;
    const int tx = threadIdx.x, ty = threadIdx.y;

    // Phase 1: vertical walks. Thread handles (h = h0+tx, w = w0+ty+8k).
    #pragma unroll
    for (int k = 0; k < 4; ++k) {
        int wl = ty + 8 * k;
        int c = (b * W_ + w0 + wl) * VPH + 32 + h0 + tx;
        float aw = 0.f, awd = 0.f;
        walk<true,  -1>(T2, c, aw, awd);   // +h (sources at h-n)
        walk<false, +1>(T3, c, aw, awd);   // -h (sources at h+n)
        s_aw [tx][wl] = aw;
        s_awd[tx][wl] = awd;
    }
    __syncthreads();

    // Phase 2: horizontal walks. Thread handles (w = w0+tx, h = h0+ty+8k).
    const float lam = lam_p[0];
    #pragma unroll
    for (int k = 0; k < 4; ++k) {
        int hl = ty + 8 * k;
        int h = h0 + hl;
        int w = w0 + tx;
        int idx = (b * H_ + h) * W_ + w;

        float din = depthin[idx];
        if (mask[idx] == 0) { out[idx] = din; continue; }

        int c = (b * H_ + h) * HPW + 32 + w;
        float aw  = s_aw [hl][tx];
        float awd = s_awd[hl][tx];
        walk<true,  -1>(T0, c, aw, awd);   // +w
        walk<false, +1>(T1, c, aw, awd);   // -w

        float o = din;
        if (aw > 0.f) {
            float lat = awd / fmaxf(aw, 1e-12f);
            if (lat > 0.f)
                o = din * (1.f - lam) + lat * lam;
        }
        out[idx] = o;
    }
}

extern "C" void kernel_launch(void* const* d_in, const int* in_sizes, int n_in,
                              void* d_out, int out_size)
{
    const float* pred_log = (const float*)d_in[0];
    const int*   mask     = (const int*)  d_in[1];
    const float* variance = (const float*)d_in[2];
    const float* depthin  = (const float*)d_in[3];
    const float* lam      = (const float*)d_in[4];
    float* out = (float*)d_out;

    dim3 blk(32, 8);
    dim3 grid(W_ / 32, H_ / 32, B_);       // 38 x 11 x 8
    prep_kernel<<<grid, blk>>>(pred_log, mask, variance, depthin);
    walk_kernel<<<grid, blk>>>(mask, depthin, lam, out);
}

// round 12
// speedup vs baseline: 4.7187x; 1.0271x over previous
#include <cuda_runtime.h>
#include <cuda_fp16.h>

#define B_ 8
#define H_ 352
#define W_ 1216
#define PLANE (H_*W_)
#define NPIX (B_*PLANE)
#define MAXR 32
#define NCHUNK 38                   // W_/32
#define SPAN 6                      // interior chunks per hscan block

#define VPH 416                     // padded height (32 | 352 | 32)
#define NVT (B_*W_*VPH)             // transposed vertical tables

// Vertical walk tables (proven): .x = exp(+/-plog_v)*mask, .y = half2(g, g*d).
// Border never written -> zero kills walks. P==0 doubles as dead-path flag.
__device__ float2 T2[NVT];  // +h, var2   TRANSPOSED (b,w,h) padded
__device__ float2 T3[NVT];  // -h, var3
// Horizontal scan table, normal (b,h,w): e = exp(+plog_h) RAW (unmasked),
// g0/g1 masked confidence weights, d = depth.
__device__ float4 TH[NPIX];
// Vertical partials (aw, awd), normal layout.
__device__ float2 PV[NPIX];

__device__ __forceinline__ float2 packv(float e, float g, float gd) {
    __half2 h2 = __floats2half2_rn(g, gd);
    float2 r; r.x = e; r.y = __uint_as_float(*reinterpret_cast<unsigned*>(&h2));
    return r;
}

__global__ void __launch_bounds__(256)
prep_kernel(const float* __restrict__ pred_log,
            const int*   __restrict__ mask,
            const float* __restrict__ var,
            const float* __restrict__ depth)
{
    __shared__ float2 s2[32][33];
    __shared__ float2 s3[32][33];

    const int b  = blockIdx.z;
    const int w0 = blockIdx.x * 32;
    const int h0 = blockIdx.y * 32;
    const int tx = threadIdx.x, ty = threadIdx.y;
    const int w  = w0 + tx;

    const float* pl0 = pred_log + (size_t)b * 2 * PLANE;
    const float* vv0 = var      + (size_t)b * 4 * PLANE;

    #pragma unroll
    for (int k = 0; k < 4; ++k) {
        int h = h0 + ty + 8 * k;
        int p = h * W_ + w;
        int idx = b * PLANE + p;

        float ph = pl0[p];
        float pv = pl0[PLANE + p];
        float m  = mask[idx] ? 1.f : 0.f;
        float v0 = vv0[p];
        float v1 = vv0[PLANE + p];
        float v2 = vv0[2 * PLANE + p];
        float v3 = vv0[3 * PLANE + p];
        float d  = depth[idx];

        float g0 = expf(-fminf(v0, 5.f)) * m;
        float g1 = expf(-fminf(v1, 5.f)) * m;
        float g2 = expf(-fminf(v2, 5.f)) * m;
        float g3 = expf(-fminf(v3, 5.f)) * m;

        TH[idx] = make_float4(expf(ph), g0, g1, d);

        s2[tx][ty + 8 * k] = packv(expf(pv)  * m, g2, g2 * d);
        s3[tx][ty + 8 * k] = packv(expf(-pv) * m, g3, g3 * d);
    }
    __syncthreads();

    #pragma unroll
    for (int k = 0; k < 4; ++k) {
        int wl = ty + 8 * k;
        int vi = (b * W_ + w0 + wl) * VPH + 32 + h0 + tx;
        T2[vi] = s2[wl][tx];
        T3[vi] = s3[wl][tx];
    }
}

// Proven vertical walk (transposed frame, batch-4, P-indicator).
template<bool INCL, int S>
__device__ __forceinline__ void walk(const float2* __restrict__ T,
                                     int c, float& aw, float& awd)
{
    float P = INCL ? 1.f : T[c].x;
    for (int n0 = 1; n0 <= MAXR; n0 += 4) {
        float2 t[4];
        #pragma unroll
        for (int j = 0; j < 4; ++j) t[j] = T[c + (n0 + j) * S];
        #pragma unroll
        for (int j = 0; j < 4; ++j) {
            unsigned u = __float_as_uint(t[j].y);
            __half2 h2 = *reinterpret_cast<__half2*>(&u);
            float2 g = __half22float2(h2);
            if (INCL) P *= t[j].x;
            awd += g.y * P;
            if (P != 0.f) aw += g.x;
            if (!INCL) P *= t[j].x;
        }
        if (P == 0.f) break;
    }
}

__global__ void __launch_bounds__(256)
vwalk_kernel()
{
    int h = blockIdx.x * 32 + threadIdx.x;
    int w = blockIdx.y * 8  + threadIdx.y;
    int b = blockIdx.z;

    int c = (b * W_ + w) * VPH + 32 + h;
    float aw = 0.f, awd = 0.f;
    walk<true,  -1>(T2, c, aw, awd);
    walk<false, +1>(T3, c, aw, awd);

    __shared__ float2 tile[32][9];
    tile[threadIdx.x][threadIdx.y] = make_float2(aw, awd);
    __syncthreads();
    int t  = threadIdx.y * 32 + threadIdx.x;
    int hl = t >> 3, wl = t & 7;
    PV[(b * H_ + blockIdx.x * 32 + hl) * W_ + blockIdx.y * 8 + wl] = tile[hl][wl];
}

__device__ __forceinline__ float wsum(float x, int lane) {
    #pragma unroll
    for (int d = 1; d < 32; d <<= 1) {
        float o = __shfl_up_sync(0xFFFFFFFFu, x, d);
        if (lane >= d) x += o;
    }
    return x;
}

// Horizontal O(1) scan kernel. Block: 8 warps scan chunks span*6-1 .. span*6+6
// of one row; warps 0..5 then resolve the 6 interior chunks' pixels.
__global__ void __launch_bounds__(256)
hscan_kernel(const int*   __restrict__ mask,
             const float* __restrict__ depthin,
             const float* __restrict__ lam_p,
             float*       __restrict__ out)
{
    __shared__ float S0[8][33], S1[8][33], G0[8][33], G1[8][33], QX[8][32];
    __shared__ float QT[8];
    __shared__ unsigned BMs[8];

    const int row  = blockIdx.y;            // b*H_ + h
    const int span = blockIdx.x;
    const int lane = threadIdx.x, k = threadIdx.y;
    const int c = span * SPAN + k - 1;      // this warp's chunk (may be outside)

    float e0 = 1.f, g0 = 0.f, g1 = 0.f, d = 0.f;
    if (c >= 0 && c < NCHUNK) {
        float4 t = TH[(size_t)row * W_ + c * 32 + lane];
        e0 = t.x; g0 = t.y; g1 = t.z; d = t.w;
    }
    unsigned bm = __ballot_sync(0xFFFFFFFFu, g0 > 0.f);

    // exclusive chunk-anchored product of e0
    float q = e0;
    #pragma unroll
    for (int dd = 1; dd < 32; dd <<= 1) {
        float o = __shfl_up_sync(0xFFFFFFFFu, q, dd);
        if (lane >= dd) q *= o;
    }
    float qtot = __shfl_sync(0xFFFFFFFFu, q, 31);
    float qex  = __shfl_up_sync(0xFFFFFFFFu, q, 1);
    if (lane == 0) qex = 1.f;
    float rq = __fdividef(1.f, qex);
    float gd0 = g0 * d, gd1 = g1 * d;

    float s0 = wsum(gd0 * rq, lane);
    float s1 = wsum(gd1 * rq, lane);
    float a0 = wsum(g0, lane);
    float a1 = wsum(g1, lane);

    S0[k][lane + 1] = s0;  S1[k][lane + 1] = s1;
    G0[k][lane + 1] = a0;  G1[k][lane + 1] = a1;
    QX[k][lane] = qex;
    if (lane == 0) {
        S0[k][0] = 0.f; S1[k][0] = 0.f; G0[k][0] = 0.f; G1[k][0] = 0.f;
        QT[k] = qtot;  BMs[k] = bm;
    }
    __syncthreads();

    // pixel phase: warps 0..5 -> slots 1..6 (interior chunks)
    if (k >= SPAN) return;
    const int s  = k + 1;
    const int cc = span * SPAN + k;
    if (cc >= NCHUNK) return;
    const int jl = lane;
    const int idx = row * W_ + cc * 32 + jl;

    float din = depthin[idx];
    float2 pv = PV[idx];
    if (mask[idx] == 0) { out[idx] = din; return; }

    unsigned bmp = BMs[s - 1], bmc = BMs[s], bmn = BMs[s + 1];
    unsigned u = __funnelshift_r(bmp, bmc, jl);                     // bits j-32..j-1
    int lim0 = __clz(~u);                                           // leading ones
    unsigned v = (jl == 31) ? bmn : __funnelshift_r(bmc, bmn, jl + 1); // bits j+1..j+32
    unsigned nv = ~v;
    int lim1 = nv ? (__ffs(nv) - 1) : 32;

    int l0c = min(lim0, jl);        int ex0 = lim0 - l0c;
    int l1c = min(lim1, 31 - jl);   int ex1 = lim1 - l1c;

    float aw  = pv.x;
    float awd = pv.y;
    float qj  = QX[s][jl];

    float sum = S0[s][jl] - S0[s][jl - l0c];
    float sg  = G0[s][jl] - G0[s][jl - l0c];
    if (ex0 > 0) {
        sum += QT[s - 1] * (S0[s - 1][32] - S0[s - 1][32 - ex0]);
        sg  += G0[s - 1][32] - G0[s - 1][32 - ex0];
    }
    sum += S1[s][jl + 1 + l1c] - S1[s][jl + 1];
    sg  += G1[s][jl + 1 + l1c] - G1[s][jl + 1];
    if (ex1 > 0) {
        sum += __fdividef(S1[s + 1][ex1], QT[s]);
        sg  += G1[s + 1][ex1];
    }
    aw  += sg;
    awd += qj * sum;

    float o = din;
    if (aw > 0.f) {
        float lat = awd / fmaxf(aw, 1e-12f);
        if (lat > 0.f) {
            float lam = lam_p[0];
            o = din * (1.f - lam) + lat * lam;
        }
    }
    out[idx] = o;
}

extern "C" void kernel_launch(void* const* d_in, const int* in_sizes, int n_in,
                              void* d_out, int out_size)
{
    const float* pred_log = (const float*)d_in[0];
    const int*   mask     = (const int*)  d_in[1];
    const float* variance = (const float*)d_in[2];
    const float* depthin  = (const float*)d_in[3];
    const float* lam      = (const float*)d_in[4];
    float* out = (float*)d_out;

    dim3 blk(32, 8);
    dim3 gp(W_ / 32, H_ / 32, B_);                  // 38 x 11 x 8
    prep_kernel<<<gp, blk>>>(pred_log, mask, variance, depthin);

    dim3 gv(H_ / 32, W_ / 8, B_);                   // 11 x 152 x 8
    vwalk_kernel<<<gv, blk>>>();

    dim3 gh((NCHUNK + SPAN - 1) / SPAN, B_ * H_);   // 7 x 2816
    hscan_kernel<<<gh, blk>>>(mask, depthin, lam, out);
}

// round 13
// speedup vs baseline: 5.7841x; 1.2258x over previous
#include <cuda_runtime.h>
#include <cuda_fp16.h>

#define B_ 8
#define H_ 352
#define W_ 1216
#define PLANE (H_*W_)
#define NPIX (B_*PLANE)
#define MAXR 32
#define NCHUNK 38                   // W_/32 horizontal chunks
#define NCHV 11                     // H_/32 vertical chunks
#define SPAN 6                      // interior chunks per hscan block

// Transposed (b,w,h) vertical scan tables:
//   TVE = exp(+plog_v) RAW ; TVG = (bits half2(g2, g2*d), bits half2(g3, g3*d))
__device__ float  TVE[NPIX];
__device__ float2 TVG[NPIX];
// Horizontal scan table, normal (b,h,w): e = exp(+plog_h) RAW, g0/g1 masked, d.
__device__ float4 TH[NPIX];
// Vertical partials (aw, awd), normal layout.
__device__ float2 PV[NPIX];

__global__ void __launch_bounds__(256)
prep_kernel(const float* __restrict__ pred_log,
            const int*   __restrict__ mask,
            const float* __restrict__ var,
            const float* __restrict__ depth)
{
    __shared__ float  s_e[32][33];
    __shared__ float2 s_g[32][33];

    const int b  = blockIdx.z;
    const int w0 = blockIdx.x * 32;
    const int h0 = blockIdx.y * 32;
    const int tx = threadIdx.x, ty = threadIdx.y;
    const int w  = w0 + tx;

    const float* pl0 = pred_log + (size_t)b * 2 * PLANE;
    const float* vv0 = var      + (size_t)b * 4 * PLANE;

    #pragma unroll
    for (int k = 0; k < 4; ++k) {
        int h = h0 + ty + 8 * k;
        int p = h * W_ + w;
        int idx = b * PLANE + p;

        float ph = pl0[p];
        float pv = pl0[PLANE + p];
        float m  = mask[idx] ? 1.f : 0.f;
        float v0 = vv0[p];
        float v1 = vv0[PLANE + p];
        float v2 = vv0[2 * PLANE + p];
        float v3 = vv0[3 * PLANE + p];
        float d  = depth[idx];

        float g0 = expf(-fminf(v0, 5.f)) * m;
        float g1 = expf(-fminf(v1, 5.f)) * m;
        float g2 = expf(-fminf(v2, 5.f)) * m;
        float g3 = expf(-fminf(v3, 5.f)) * m;

        TH[idx] = make_float4(expf(ph), g0, g1, d);

        __half2 ha = __floats2half2_rn(g2, g2 * d);
        __half2 hb = __floats2half2_rn(g3, g3 * d);
        s_e[tx][ty + 8 * k] = expf(pv);
        s_g[tx][ty + 8 * k] = make_float2(
            __uint_as_float(*reinterpret_cast<unsigned*>(&ha)),
            __uint_as_float(*reinterpret_cast<unsigned*>(&hb)));
    }
    __syncthreads();

    #pragma unroll
    for (int k = 0; k < 4; ++k) {
        int wl = ty + 8 * k;
        size_t vi = ((size_t)b * W_ + w0 + wl) * H_ + h0 + tx;   // contiguous in tx
        TVE[vi] = s_e[wl][tx];
        TVG[vi] = s_g[wl][tx];
    }
}

__device__ __forceinline__ float wsum(float x, int lane) {
    #pragma unroll
    for (int d = 1; d < 32; d <<= 1) {
        float o = __shfl_up_sync(0xFFFFFFFFu, x, d);
        if (lane >= d) x += o;
    }
    return x;
}

// Scan one 32-px chunk: fills prefix arrays S0/S1 (gd/qex) and G0/G1 (g),
// returns lane's exclusive anchored product qex, chunk total qt, alive bitmap.
__device__ __forceinline__ void scan_chunk_v(size_t gbase, int lane,
                                             float* S0r, float* S1r,
                                             float* G0r, float* G1r,
                                             float& qex, float& qt, unsigned& bm)
{
    float  e = TVE[gbase + lane];
    float2 G = TVG[gbase + lane];
    unsigned ua = __float_as_uint(G.x);
    unsigned ub = __float_as_uint(G.y);
    float2 ga = __half22float2(*reinterpret_cast<__half2*>(&ua));  // (g2, g2*d)
    float2 gb = __half22float2(*reinterpret_cast<__half2*>(&ub));  // (g3, g3*d)

    bm = __ballot_sync(0xFFFFFFFFu, ga.x > 0.f);

    float q = e;
    #pragma unroll
    for (int dd = 1; dd < 32; dd <<= 1) {
        float o = __shfl_up_sync(0xFFFFFFFFu, q, dd);
        if (lane >= dd) q *= o;
    }
    qt  = __shfl_sync(0xFFFFFFFFu, q, 31);
    qex = __shfl_up_sync(0xFFFFFFFFu, q, 1);
    if (lane == 0) qex = 1.f;
    float rq = __fdividef(1.f, qex);

    S0r[lane + 1] = wsum(ga.y * rq, lane);
    S1r[lane + 1] = wsum(gb.y * rq, lane);
    G0r[lane + 1] = wsum(ga.x, lane);
    G1r[lane + 1] = wsum(gb.x, lane);
    if (lane == 0) { S0r[0] = 0.f; S1r[0] = 0.f; G0r[0] = 0.f; G1r[0] = 0.f; }
}

// Vertical O(1) scan: block = 8 warps x 8 adjacent columns; each warp rolls
// down its column over the 11 h-chunks with a 3-slot ring of prefix arrays.
__global__ void __launch_bounds__(256)
vscan_kernel()
{
    __shared__ float S0[8][3][33], S1[8][3][33], G0[8][3][33], G1[8][3][33];
    __shared__ float2 ST[32][8];       // [h_local][w_local] staging

    const int lane = threadIdx.x, wp = threadIdx.y;
    const int b = blockIdx.y, w0 = blockIdx.x * 8;
    const size_t colbase = ((size_t)b * W_ + w0 + wp) * H_;

    // slot 2 = chunk -1 (all dead / zero)
    S0[wp][2][lane + 1] = 0.f; S1[wp][2][lane + 1] = 0.f;
    G0[wp][2][lane + 1] = 0.f; G1[wp][2][lane + 1] = 0.f;
    if (lane == 0) { S0[wp][2][0] = 0.f; S1[wp][2][0] = 0.f; G0[wp][2][0] = 0.f; G1[wp][2][0] = 0.f; }

    float qex_c, qt_c, qt_p = 1.f, qex_n, qt_n;
    unsigned bm_p = 0u, bm_c, bm_n;
    scan_chunk_v(colbase, lane, S0[wp][0], S1[wp][0], G0[wp][0], G1[wp][0],
                 qex_c, qt_c, bm_c);

    for (int c = 0; c < NCHV; ++c) {
        int sn = (c + 1) % 3;
        if (c + 1 < NCHV) {
            scan_chunk_v(colbase + (size_t)(c + 1) * 32, lane,
                         S0[wp][sn], S1[wp][sn], G0[wp][sn], G1[wp][sn],
                         qex_n, qt_n, bm_n);
        } else {
            S0[wp][sn][lane + 1] = 0.f; S1[wp][sn][lane + 1] = 0.f;
            G0[wp][sn][lane + 1] = 0.f; G1[wp][sn][lane + 1] = 0.f;
            if (lane == 0) { S0[wp][sn][0] = 0.f; S1[wp][sn][0] = 0.f;
                             G0[wp][sn][0] = 0.f; G1[wp][sn][0] = 0.f; }
            qex_n = 1.f; qt_n = 1.f; bm_n = 0u;
        }
        __syncwarp();

        int sp = (c + 2) % 3, sc = c % 3;
        unsigned u = __funnelshift_r(bm_p, bm_c, lane);            // alive[j-32..j-1]
        int lim0 = __clz(~u);
        unsigned v = (lane == 31) ? bm_n : __funnelshift_r(bm_c, bm_n, lane + 1);
        unsigned nv = ~v;
        int lim1 = nv ? (__ffs(nv) - 1) : 32;

        int l0c = min(lim0, lane);      int ex0 = lim0 - l0c;
        int l1c = min(lim1, 31 - lane); int ex1 = lim1 - l1c;

        float sum = (S0[wp][sc][lane] - S0[wp][sc][lane - l0c])
                  + (S1[wp][sc][lane + 1 + l1c] - S1[wp][sc][lane + 1]);
        float sg  = (G0[wp][sc][lane] - G0[wp][sc][lane - l0c])
                  + (G1[wp][sc][lane + 1 + l1c] - G1[wp][sc][lane + 1]);
        if (ex0 > 0) {
            sum += qt_p * (S0[wp][sp][32] - S0[wp][sp][32 - ex0]);
            sg  += G0[wp][sp][32] - G0[wp][sp][32 - ex0];
        }
        if (ex1 > 0) {
            sum += __fdividef(S1[wp][sn][ex1], qt_c);
            sg  += G1[wp][sn][ex1];
        }
        ST[lane][wp] = make_float2(sg, qex_c * sum);
        __syncthreads();
        int t = wp * 32 + lane;
        int hl = t >> 3, wl = t & 7;
        PV[((size_t)b * H_ + c * 32 + hl) * W_ + w0 + wl] = ST[hl][wl];
        __syncthreads();

        bm_p = bm_c; bm_c = bm_n; qt_p = qt_c; qt_c = qt_n; qex_c = qex_n;
    }
}

// Horizontal O(1) scan kernel (unchanged from R12): 8 warps scan 8 chunks
// (6 interior + 2 halo) of one row; warps 0..5 resolve pixels + blend.
__global__ void __launch_bounds__(256)
hscan_kernel(const int*   __restrict__ mask,
             const float* __restrict__ depthin,
             const float* __restrict__ lam_p,
             float*       __restrict__ out)
{
    __shared__ float S0[8][33], S1[8][33], G0[8][33], G1[8][33], QX[8][32];
    __shared__ float QT[8];
    __shared__ unsigned BMs[8];

    const int row  = blockIdx.y;
    const int span = blockIdx.x;
    const int lane = threadIdx.x, k = threadIdx.y;
    const int c = span * SPAN + k - 1;

    float e0 = 1.f, g0 = 0.f, g1 = 0.f, d = 0.f;
    if (c >= 0 && c < NCHUNK) {
        float4 t = TH[(size_t)row * W_ + c * 32 + lane];
        e0 = t.x; g0 = t.y; g1 = t.z; d = t.w;
    }
    unsigned bm = __ballot_sync(0xFFFFFFFFu, g0 > 0.f);

    float q = e0;
    #pragma unroll
    for (int dd = 1; dd < 32; dd <<= 1) {
        float o = __shfl_up_sync(0xFFFFFFFFu, q, dd);
        if (lane >= dd) q *= o;
    }
    float qtot = __shfl_sync(0xFFFFFFFFu, q, 31);
    float qex  = __shfl_up_sync(0xFFFFFFFFu, q, 1);
    if (lane == 0) qex = 1.f;
    float rq = __fdividef(1.f, qex);

    S0[k][lane + 1] = wsum(g0 * d * rq, lane);
    S1[k][lane + 1] = wsum(g1 * d * rq, lane);
    G0[k][lane + 1] = wsum(g0, lane);
    G1[k][lane + 1] = wsum(g1, lane);
    QX[k][lane] = qex;
    if (lane == 0) {
        S0[k][0] = 0.f; S1[k][0] = 0.f; G0[k][0] = 0.f; G1[k][0] = 0.f;
        QT[k] = qtot;  BMs[k] = bm;
    }
    __syncthreads();

    if (k >= SPAN) return;
    const int s  = k + 1;
    const int cc = span * SPAN + k;
    if (cc >= NCHUNK) return;
    const int jl = lane;
    const int idx = row * W_ + cc * 32 + jl;

    float din = depthin[idx];
    float2 pv = PV[idx];
    if (mask[idx] == 0) { out[idx] = din; return; }

    unsigned bmp = BMs[s - 1], bmc = BMs[s], bmn = BMs[s + 1];
    unsigned u = __funnelshift_r(bmp, bmc, jl);
    int lim0 = __clz(~u);
    unsigned v = (jl == 31) ? bmn : __funnelshift_r(bmc, bmn, jl + 1);
    unsigned nv = ~v;
    int lim1 = nv ? (__ffs(nv) - 1) : 32;

    int l0c = min(lim0, jl);        int ex0 = lim0 - l0c;
    int l1c = min(lim1, 31 - jl);   int ex1 = lim1 - l1c;

    float aw  = pv.x;
    float awd = pv.y;
    float qj  = QX[s][jl];

    float sum = S0[s][jl] - S0[s][jl - l0c];
    float sg  = G0[s][jl] - G0[s][jl - l0c];
    if (ex0 > 0) {
        sum += QT[s - 1] * (S0[s - 1][32] - S0[s - 1][32 - ex0]);
        sg  += G0[s - 1][32] - G0[s - 1][32 - ex0];
    }
    sum += S1[s][jl + 1 + l1c] - S1[s][jl + 1];
    sg  += G1[s][jl + 1 + l1c] - G1[s][jl + 1];
    if (ex1 > 0) {
        sum += __fdividef(S1[s + 1][ex1], QT[s]);
        sg  += G1[s + 1][ex1];
    }
    aw  += sg;
    awd += qj * sum;

    float o = din;
    if (aw > 0.f) {
        float lat = awd / fmaxf(aw, 1e-12f);
        if (lat > 0.f) {
            float lam = lam_p[0];
            o = din * (1.f - lam) + lat * lam;
        }
    }
    out[idx] = o;
}

extern "C" void kernel_launch(void* const* d_in, const int* in_sizes, int n_in,
                              void* d_out, int out_size)
{
    const float* pred_log = (const float*)d_in[0];
    const int*   mask     = (const int*)  d_in[1];
    const float* variance = (const float*)d_in[2];
    const float* depthin  = (const float*)d_in[3];
    const float* lam      = (const float*)d_in[4];
    float* out = (float*)d_out;

    dim3 blk(32, 8);
    dim3 gp(W_ / 32, H_ / 32, B_);                  // 38 x 11 x 8
    prep_kernel<<<gp, blk>>>(pred_log, mask, variance, depthin);

    dim3 gv(W_ / 8, B_);                            // 152 x 8
    vscan_kernel<<<gv, blk>>>();

    dim3 gh((NCHUNK + SPAN - 1) / SPAN, B_ * H_);   // 7 x 2816
    hscan_kernel<<<gh, blk>>>(mask, depthin, lam, out);
}

// round 14
// speedup vs baseline: 6.5677x; 1.1355x over previous
#include <cuda_runtime.h>

#define B_ 8
#define H_ 352
#define W_ 1216
#define PLANE (H_*W_)
#define NPIX (B_*PLANE)
#define NCHUNK 38                   // W_/32 horizontal chunks
#define NCHV 11                     // H_/32 vertical chunks
#define SPAN 6                      // interior chunks per hscan block

// Vertical partials (aw, awd), normal (b,h,w) layout.
__device__ float2 PV[NPIX];

__device__ __forceinline__ float wsum(float x, int lane) {
    #pragma unroll
    for (int d = 1; d < 32; d <<= 1) {
        float o = __shfl_up_sync(0xFFFFFFFFu, x, d);
        if (lane >= d) x += o;
    }
    return x;
}

// ---------------------------------------------------------------------------
// Vertical O(1) scan. Block = 8 warps x 8 adjacent columns. Per h-chunk:
// cooperative coalesced tile load of raw inputs -> smem (computing e/g/gd),
// per-warp column scan (shared anchored product q for both directions),
// O(1) window resolve, coalesced PV write.
// ---------------------------------------------------------------------------
__global__ void __launch_bounds__(256)
vscan_kernel(const float* __restrict__ pred_log,
             const int*   __restrict__ mask,
             const float* __restrict__ var,
             const float* __restrict__ depth)
{
    __shared__ float S0[8][3][33], S1[8][3][33], G0[8][3][33], G1[8][3][33];
    __shared__ float s_e[32][9], s_g2[32][9], s_gd2[32][9], s_g3[32][9], s_gd3[32][9];
    __shared__ float2 ST[32][8];

    const int lane = threadIdx.x, wp = threadIdx.y;
    const int t  = wp * 32 + lane;
    const int hl = t >> 3, wl = t & 7;          // tile-load coords
    const int b  = blockIdx.y, w0 = blockIdx.x * 8;

    const float* pvp = pred_log + (size_t)b * 2 * PLANE + PLANE;
    const float* v2p = var   + (size_t)b * 4 * PLANE + 2 * PLANE;
    const float* v3p = var   + (size_t)b * 4 * PLANE + 3 * PLANE;
    const float* dp  = depth + (size_t)b * PLANE;
    const int*   mp  = mask  + (size_t)b * PLANE;

    // slot 2 = chunk -1 (zero)
    S0[wp][2][lane + 1] = 0.f; S1[wp][2][lane + 1] = 0.f;
    G0[wp][2][lane + 1] = 0.f; G1[wp][2][lane + 1] = 0.f;
    if (lane == 0) { S0[wp][2][0] = 0.f; S1[wp][2][0] = 0.f;
                     G0[wp][2][0] = 0.f; G1[wp][2][0] = 0.f; }

#define LOAD_TILE(c) do {                                   \
        size_t p = (size_t)((c) * 32 + hl) * W_ + w0 + wl;  \
        float pv = pvp[p];                                  \
        float m  = mp[p] ? 1.f : 0.f;                       \
        float g2 = __expf(-fminf(v2p[p], 5.f)) * m;         \
        float g3 = __expf(-fminf(v3p[p], 5.f)) * m;         \
        float dd = dp[p];                                   \
        s_e [hl][wl] = __expf(pv);                          \
        s_g2[hl][wl] = g2;  s_gd2[hl][wl] = g2 * dd;        \
        s_g3[hl][wl] = g3;  s_gd3[hl][wl] = g3 * dd;        \
    } while (0)

#define SCAN_SLOT(sl, QEX, QT, BM) do {                                  \
        float e  = s_e [lane][wp];                                       \
        float ga = s_g2[lane][wp], gda = s_gd2[lane][wp];                \
        float gb = s_g3[lane][wp], gdb = s_gd3[lane][wp];                \
        BM = __ballot_sync(0xFFFFFFFFu, ga > 0.f);                       \
        float q = e;                                                     \
        _Pragma("unroll")                                                \
        for (int dd = 1; dd < 32; dd <<= 1) {                            \
            float o = __shfl_up_sync(0xFFFFFFFFu, q, dd);                \
            if (lane >= dd) q *= o;                                      \
        }                                                                \
        QT  = __shfl_sync(0xFFFFFFFFu, q, 31);                           \
        QEX = __shfl_up_sync(0xFFFFFFFFu, q, 1);                         \
        if (lane == 0) QEX = 1.f;                                        \
        float rq = __fdividef(1.f, QEX);                                 \
        S0[wp][sl][lane + 1] = wsum(gda * rq, lane);                     \
        S1[wp][sl][lane + 1] = wsum(gdb * rq, lane);                     \
        G0[wp][sl][lane + 1] = wsum(ga, lane);                           \
        G1[wp][sl][lane + 1] = wsum(gb, lane);                           \
        if (lane == 0) { S0[wp][sl][0] = 0.f; S1[wp][sl][0] = 0.f;       \
                         G0[wp][sl][0] = 0.f; G1[wp][sl][0] = 0.f; }     \
        __syncwarp();                                                    \
    } while (0)

    float qex_c, qt_c, qt_p = 1.f, qex_n, qt_n;
    unsigned bm_p = 0u, bm_c, bm_n;

    LOAD_TILE(0);
    __syncthreads();
    SCAN_SLOT(0, qex_c, qt_c, bm_c);

    for (int c = 0; c < NCHV; ++c) {
        int sn = (c + 1) % 3;
        if (c + 1 < NCHV) {
            __syncthreads();               // all warps done with current tile
            LOAD_TILE(c + 1);
            __syncthreads();
            SCAN_SLOT(sn, qex_n, qt_n, bm_n);
        } else {
            S0[wp][sn][lane + 1] = 0.f; S1[wp][sn][lane + 1] = 0.f;
            G0[wp][sn][lane + 1] = 0.f; G1[wp][sn][lane + 1] = 0.f;
            if (lane == 0) { S0[wp][sn][0] = 0.f; S1[wp][sn][0] = 0.f;
                             G0[wp][sn][0] = 0.f; G1[wp][sn][0] = 0.f; }
            qex_n = 1.f; qt_n = 1.f; bm_n = 0u;
            __syncwarp();
        }

        int sp = (c + 2) % 3, sc = c % 3;
        unsigned u = __funnelshift_r(bm_p, bm_c, lane);            // alive[j-32..j-1]
        int lim0 = __clz(~u);
        unsigned v = (lane == 31) ? bm_n : __funnelshift_r(bm_c, bm_n, lane + 1);
        unsigned nv = ~v;
        int lim1 = nv ? (__ffs(nv) - 1) : 32;

        int l0c = min(lim0, lane);      int ex0 = lim0 - l0c;
        int l1c = min(lim1, 31 - lane); int ex1 = lim1 - l1c;

        float sum = (S0[wp][sc][lane] - S0[wp][sc][lane - l0c])
                  + (S1[wp][sc][lane + 1 + l1c] - S1[wp][sc][lane + 1]);
        float sg  = (G0[wp][sc][lane] - G0[wp][sc][lane - l0c])
                  + (G1[wp][sc][lane + 1 + l1c] - G1[wp][sc][lane + 1]);
        if (ex0 > 0) {
            sum += qt_p * (S0[wp][sp][32] - S0[wp][sp][32 - ex0]);
            sg  += G0[wp][sp][32] - G0[wp][sp][32 - ex0];
        }
        if (ex1 > 0) {
            sum += __fdividef(S1[wp][sn][ex1], qt_c);
            sg  += G1[wp][sn][ex1];
        }
        ST[lane][wp] = make_float2(sg, qex_c * sum);
        __syncthreads();
        PV[((size_t)b * H_ + c * 32 + hl) * W_ + w0 + wl] = ST[hl][wl];
        __syncthreads();

        bm_p = bm_c; bm_c = bm_n; qt_p = qt_c; qt_c = qt_n; qex_c = qex_n;
    }
#undef LOAD_TILE
#undef SCAN_SLOT
}

// ---------------------------------------------------------------------------
// Horizontal O(1) scan: 8 warps scan 8 chunks (6 interior + 2 halo) of one
// row directly from raw inputs; warps 0..5 resolve pixels, combine PV, blend.
// ---------------------------------------------------------------------------
__global__ void __launch_bounds__(256)
hscan_kernel(const float* __restrict__ pred_log,
             const int*   __restrict__ mask,
             const float* __restrict__ var,
             const float* __restrict__ depthin,
             const float* __restrict__ lam_p,
             float*       __restrict__ out)
{
    __shared__ float S0[8][33], S1[8][33], G0[8][33], G1[8][33], QX[8][32];
    __shared__ float QT[8];
    __shared__ unsigned BMs[8];

    const int row  = blockIdx.y;            // b*H_ + h
    const int b    = row / H_;
    const int span = blockIdx.x;
    const int lane = threadIdx.x, k = threadIdx.y;
    const int c = span * SPAN + k - 1;

    const size_t rowoff  = (size_t)row * W_;            // (B,1,H,W) row base
    const size_t inplane = rowoff - (size_t)b * PLANE;  // h*W_

    float e0 = 1.f, g0 = 0.f, g1 = 0.f, d = 0.f;
    if (c >= 0 && c < NCHUNK) {
        int col = c * 32 + lane;
        size_t p = inplane + col;
        float ph = pred_log[(size_t)b * 2 * PLANE + p];
        float m  = mask[rowoff + col] ? 1.f : 0.f;
        float v0 = var[(size_t)b * 4 * PLANE + p];
        float v1 = var[(size_t)b * 4 * PLANE + PLANE + p];
        d  = depthin[rowoff + col];
        e0 = __expf(ph);
        g0 = __expf(-fminf(v0, 5.f)) * m;
        g1 = __expf(-fminf(v1, 5.f)) * m;
    }
    unsigned bm = __ballot_sync(0xFFFFFFFFu, g0 > 0.f);

    float q = e0;
    #pragma unroll
    for (int dd = 1; dd < 32; dd <<= 1) {
        float o = __shfl_up_sync(0xFFFFFFFFu, q, dd);
        if (lane >= dd) q *= o;
    }
    float qtot = __shfl_sync(0xFFFFFFFFu, q, 31);
    float qex  = __shfl_up_sync(0xFFFFFFFFu, q, 1);
    if (lane == 0) qex = 1.f;
    float rq = __fdividef(1.f, qex);

    S0[k][lane + 1] = wsum(g0 * d * rq, lane);
    S1[k][lane + 1] = wsum(g1 * d * rq, lane);
    G0[k][lane + 1] = wsum(g0, lane);
    G1[k][lane + 1] = wsum(g1, lane);
    QX[k][lane] = qex;
    if (lane == 0) {
        S0[k][0] = 0.f; S1[k][0] = 0.f; G0[k][0] = 0.f; G1[k][0] = 0.f;
        QT[k] = qtot;  BMs[k] = bm;
    }
    __syncthreads();

    if (k >= SPAN) return;
    const int s  = k + 1;
    const int cc = span * SPAN + k;
    if (cc >= NCHUNK) return;
    const int jl = lane;
    const size_t idx = rowoff + cc * 32 + jl;

    float din = depthin[idx];
    unsigned bmc = BMs[s];
    if (!((bmc >> jl) & 1u)) { out[idx] = din; return; }   // masked pixel

    float2 pv = PV[idx];
    unsigned bmp = BMs[s - 1], bmn = BMs[s + 1];
    unsigned u = __funnelshift_r(bmp, bmc, jl);
    int lim0 = __clz(~u);
    unsigned v = (jl == 31) ? bmn : __funnelshift_r(bmc, bmn, jl + 1);
    unsigned nv = ~v;
    int lim1 = nv ? (__ffs(nv) - 1) : 32;

    int l0c = min(lim0, jl);        int ex0 = lim0 - l0c;
    int l1c = min(lim1, 31 - jl);   int ex1 = lim1 - l1c;

    float aw  = pv.x;
    float awd = pv.y;
    float qj  = QX[s][jl];

    float sum = S0[s][jl] - S0[s][jl - l0c];
    float sg  = G0[s][jl] - G0[s][jl - l0c];
    if (ex0 > 0) {
        sum += QT[s - 1] * (S0[s - 1][32] - S0[s - 1][32 - ex0]);
        sg  += G0[s - 1][32] - G0[s - 1][32 - ex0];
    }
    sum += S1[s][jl + 1 + l1c] - S1[s][jl + 1];
    sg  += G1[s][jl + 1 + l1c] - G1[s][jl + 1];
    if (ex1 > 0) {
        sum += __fdividef(S1[s + 1][ex1], QT[s]);
        sg  += G1[s + 1][ex1];
    }
    aw  += sg;
    awd += qj * sum;

    float o = din;
    if (aw > 0.f) {
        float lat = awd / fmaxf(aw, 1e-12f);
        if (lat > 0.f) {
            float lam = lam_p[0];
            o = din * (1.f - lam) + lat * lam;
        }
    }
    out[idx] = o;
}

extern "C" void kernel_launch(void* const* d_in, const int* in_sizes, int n_in,
                              void* d_out, int out_size)
{
    const float* pred_log = (const float*)d_in[0];
    const int*   mask     = (const int*)  d_in[1];
    const float* variance = (const float*)d_in[2];
    const float* depthin  = (const float*)d_in[3];
    const float* lam      = (const float*)d_in[4];
    float* out = (float*)d_out;

    dim3 blk(32, 8);
    dim3 gv(W_ / 8, B_);                            // 152 x 8
    vscan_kernel<<<gv, blk>>>(pred_log, mask, variance, depthin);

    dim3 gh((NCHUNK + SPAN - 1) / SPAN, B_ * H_);   // 7 x 2816
    hscan_kernel<<<gh, blk>>>(pred_log, mask, variance, depthin, lam, out);
}